// round 7
// baseline (speedup 1.0000x reference)
#include <cuda_runtime.h>
#include <math.h>

#define NB 64
#define NP 24564
#define NM 16
#define NC 21
#define BP_CHUNK 2048   // priors per k_bestprior block (12 chunks cover 24576)

// ---------------- scratch (device globals; zero-initialized at load) ----------------
__device__ float              g_mined[NB * NP];  // loss_c_mined (0 for pos)
__device__ unsigned long long g_bp[NB * NM];     // best prior key per truth
__device__ float              g_loss_l;
__device__ float              g_loss_c;
__device__ float              g_pos_conf[NB];
__device__ int                g_num_pos[NB];

// ---------------- best prior per truth: register-local keys, one reduction ----------------
__global__ void k_bestprior(const float* __restrict__ priors,
                            const float* __restrict__ targets) {
    int b   = blockIdx.y;
    int tid = threadIdx.x;
    __shared__ float s_tr[NM][4];
    __shared__ float s_area[NM];

    if (tid < NM * 4) {
        int m = tid >> 2, c = tid & 3;
        s_tr[m][c] = targets[(b * NM + m) * 5 + c];
    }
    __syncthreads();
    if (tid < NM)
        s_area[tid] = (s_tr[tid][2] - s_tr[tid][0]) * (s_tr[tid][3] - s_tr[tid][1]);
    __syncthreads();

    unsigned long long key[NM];
    #pragma unroll
    for (int j = 0; j < NM; j++) key[j] = 0ull;

    int p0   = blockIdx.x * BP_CHUNK;
    int pend = p0 + BP_CHUNK; if (pend > NP) pend = NP;
    for (int p = p0 + tid; p < pend; p += 256) {
        float4 pr = ((const float4*)priors)[p];
        float px1 = pr.x - pr.z * 0.5f, py1 = pr.y - pr.w * 0.5f;
        float px2 = pr.x + pr.z * 0.5f, py2 = pr.y + pr.w * 0.5f;
        float pa  = (px2 - px1) * (py2 - py1);
        unsigned long long lowbits = (unsigned long long)(0xFFFFFFFFu - (unsigned)p);
        #pragma unroll
        for (int j = 0; j < NM; j++) {
            float iw = fminf(s_tr[j][2], px2) - fmaxf(s_tr[j][0], px1);
            float ih = fminf(s_tr[j][3], py2) - fmaxf(s_tr[j][1], py1);
            iw = fmaxf(iw, 0.f); ih = fmaxf(ih, 0.f);
            float inter = iw * ih;
            float iou   = inter / (s_area[j] + pa - inter);
            unsigned long long k2 =
                ((unsigned long long)__float_as_uint(iou) << 32) | lowbits;
            if (k2 > key[j]) key[j] = k2;       // tie -> smaller p (first occurrence)
        }
    }

    int lane = tid & 31;
    #pragma unroll
    for (int j = 0; j < NM; j++) {
        unsigned long long k = key[j];
        #pragma unroll
        for (int off = 16; off; off >>= 1) {
            unsigned long long o = __shfl_down_sync(0xFFFFFFFFu, k, off);
            if (o > k) k = o;
        }
        if (lane == 0) atomicMax(&g_bp[b * NM + j], k);
    }
}

// ---------------- fused match + losses (HBM-bound heavy pass) ----------------
__global__ void k_loss(const float* __restrict__ loc,
                       const float* __restrict__ conf,
                       const float* __restrict__ priors,
                       const float* __restrict__ targets) {
    int b   = blockIdx.y;
    int tid = threadIdx.x;
    int p0  = blockIdx.x * 256;
    __shared__ float    s_conf[256 * NC];
    __shared__ float    s_tr[NM][5];
    __shared__ float    s_area[NM];
    __shared__ unsigned s_op[NM];               // forced prior index per truth
    __shared__ float    r_ll[8], r_pc[8];
    __shared__ int      r_np[8];

    int nvalid = NP - p0; if (nvalid > 256) nvalid = 256;
    // (b*NP+p0)*21 floats is 16B-aligned and nvalid*21 divisible by 4 -> pure float4.
    const float4* src4 = (const float4*)(conf + ((size_t)b * NP + p0) * NC);
    float4*       dst4 = (float4*)s_conf;
    int n4 = (nvalid * NC) >> 2;
    for (int i = tid; i < n4; i += 256) dst4[i] = src4[i];
    if (tid < NM * 5) s_tr[tid / 5][tid % 5] = targets[b * NM * 5 + tid];
    if (tid >= 32 && tid < 32 + NM) {
        int j = tid - 32;
        s_op[j] = 0xFFFFFFFFu - (unsigned)(g_bp[b * NM + j] & 0xFFFFFFFFull);
    }
    __syncthreads();
    if (tid < NM)
        s_area[tid] = (s_tr[tid][2] - s_tr[tid][0]) * (s_tr[tid][3] - s_tr[tid][1]);
    __syncthreads();

    int p = p0 + tid;
    float my_ll = 0.f, my_pc = 0.f;
    int   my_np = 0;

    if (p < NP) {
        // inline best-truth match for this prior
        float4 pr = ((const float4*)priors)[p];
        float px1 = pr.x - pr.z * 0.5f, py1 = pr.y - pr.w * 0.5f;
        float px2 = pr.x + pr.z * 0.5f, py2 = pr.y + pr.w * 0.5f;
        float pa  = (px2 - px1) * (py2 - py1);
        float bestv = -1.f;
        int   bestj = 0;
        #pragma unroll
        for (int j = 0; j < NM; j++) {
            float iw = fminf(s_tr[j][2], px2) - fmaxf(s_tr[j][0], px1);
            float ih = fminf(s_tr[j][3], py2) - fmaxf(s_tr[j][1], py1);
            iw = fmaxf(iw, 0.f); ih = fmaxf(ih, 0.f);
            float inter = iw * ih;
            float iou   = inter / (s_area[j] + pa - inter);
            if (iou > bestv) { bestv = iou; bestj = j; }  // strict > : first occurrence
        }
        bool forced = false;
        #pragma unroll
        for (int j = 0; j < NM; j++)                       // ascending -> last-wins
            if (s_op[j] == (unsigned)p) { bestj = j; forced = true; }
        bool pos = forced || (bestv >= 0.5f);
        int  ct  = pos ? ((int)s_tr[bestj][4] + 1) : 0;

        // logsumexp without max-subtraction (conf ~ N(0,1); fp32 safe)
        const float* cr = &s_conf[tid * NC];
        float s = 0.f;
        #pragma unroll
        for (int c = 0; c < NC; c++) s += __expf(cr[c]);
        float lca = __logf(s) - cr[ct];

        g_mined[b * NP + p] = pos ? 0.f : lca;

        if (pos) {
            my_pc = lca;
            my_np = 1;
            float4 ld = ((const float4*)loc)[(size_t)b * NP + p];
            float tx1 = s_tr[bestj][0], ty1 = s_tr[bestj][1];
            float tx2 = s_tr[bestj][2], ty2 = s_tr[bestj][3];
            float gx = ((tx1 + tx2) * 0.5f - pr.x) / (0.1f * pr.z);
            float gy = ((ty1 + ty2) * 0.5f - pr.y) / (0.1f * pr.w);
            float gw = logf((tx2 - tx1) / pr.z) / 0.2f;
            float gh = logf((ty2 - ty1) / pr.w) / 0.2f;
            float d, a;
            d = ld.x - gx; a = fabsf(d); my_ll += (a < 1.f) ? (0.5f * d * d) : (a - 0.5f);
            d = ld.y - gy; a = fabsf(d); my_ll += (a < 1.f) ? (0.5f * d * d) : (a - 0.5f);
            d = ld.z - gw; a = fabsf(d); my_ll += (a < 1.f) ? (0.5f * d * d) : (a - 0.5f);
            d = ld.w - gh; a = fabsf(d); my_ll += (a < 1.f) ? (0.5f * d * d) : (a - 0.5f);
        }
    }

    // block reduce
    int lane = tid & 31, wp = tid >> 5;
    for (int off = 16; off; off >>= 1) {
        my_ll += __shfl_down_sync(0xFFFFFFFFu, my_ll, off);
        my_pc += __shfl_down_sync(0xFFFFFFFFu, my_pc, off);
        my_np += __shfl_down_sync(0xFFFFFFFFu, my_np, off);
    }
    if (lane == 0) { r_ll[wp] = my_ll; r_pc[wp] = my_pc; r_np[wp] = my_np; }
    __syncthreads();
    if (tid == 0) {
        float tll = 0.f, tpc = 0.f; int tnp = 0;
        #pragma unroll
        for (int w = 0; w < 8; w++) { tll += r_ll[w]; tpc += r_pc[w]; tnp += r_np[w]; }
        atomicAdd(&g_loss_l, tll);
        atomicAdd(&g_pos_conf[b], tpc);
        atomicAdd(&g_num_pos[b], tnp);
    }
}

// ---------------- hard-negative mining: radix top-k SUM per batch ----------------
__global__ void k_select() {
    int b   = blockIdx.x;
    int tid = threadIdx.x;
    __shared__ int      bins[256];
    __shared__ unsigned s_pref;
    __shared__ int      s_krem;
    __shared__ float    r_s[32];

    const float* data = &g_mined[b * NP];

    if (tid == 0) {
        s_pref = 0u;
        long long kk = 3LL * (long long)g_num_pos[b];
        if (kk > NP - 1) kk = NP - 1;
        s_krem = (int)kk;
    }
    if (tid < 256) bins[tid] = 0;
    __syncthreads();

    for (int byte = 3; byte >= 0; --byte) {
        unsigned pref = s_pref;
        int shift = byte * 8;
        #pragma unroll 4
        for (int i = tid; i < NP; i += 1024) {
            unsigned u = __float_as_uint(data[i]);   // values >= 0 -> bits monotone
            bool ok = (byte == 3) || ((u >> (shift + 8)) == pref);
            if (ok) atomicAdd(&bins[(u >> shift) & 255], 1);
        }
        __syncthreads();
        if (tid == 0) {
            int krem = s_krem, cum = 0, sel = 0;
            for (int t = 255; t >= 0; --t) {
                int c = bins[t];
                if (cum + c >= krem) { sel = t; break; }
                cum += c;
            }
            s_krem = krem - cum;
            s_pref = (s_pref << 8) | (unsigned)sel;
        }
        __syncthreads();
        if (tid < 256) bins[tid] = 0;
        __syncthreads();
    }

    unsigned thr  = s_pref;
    int      krem = s_krem;
    float s = 0.f;
    #pragma unroll 4
    for (int i = tid; i < NP; i += 1024) {
        float v = data[i];
        if (__float_as_uint(v) > thr) s += v;
    }
    int lane = tid & 31, wp = tid >> 5;
    for (int off = 16; off; off >>= 1) s += __shfl_down_sync(0xFFFFFFFFu, s, off);
    if (lane == 0) r_s[wp] = s;
    __syncthreads();
    if (tid == 0) {
        float tot = 0.f;
        #pragma unroll
        for (int w = 0; w < 32; w++) tot += r_s[w];
        tot += (float)krem * __uint_as_float(thr);   // boundary-tied elements
        tot += g_pos_conf[b];                        // pos contribution (pos | neg union)
        atomicAdd(&g_loss_c, tot);
    }
}

// ---------------- finalize + reset accumulators for next graph replay ----------------
__global__ void k_final(float* __restrict__ out) {
    int tid = threadIdx.x;
    if (tid == 0) {
        int n = 0;
        for (int b = 0; b < NB; b++) n += g_num_pos[b];
        float fn = (float)n;
        out[0] = g_loss_l / fn;
        out[1] = g_loss_c / fn;
    }
    __syncthreads();
    // reset so every replay starts from a clean state
    if (tid < NB * NM) g_bp[tid] = 0ull;
    if (tid < NB) { g_pos_conf[tid] = 0.f; g_num_pos[tid] = 0; }
    if (tid == 0) { g_loss_l = 0.f; g_loss_c = 0.f; }
}

// ---------------- launch ----------------
extern "C" void kernel_launch(void* const* d_in, const int* in_sizes, int n_in,
                              void* d_out, int out_size) {
    const float* loc     = (const float*)d_in[0];
    const float* conf    = (const float*)d_in[1];
    const float* priors  = (const float*)d_in[2];
    const float* targets = (const float*)d_in[3];
    float*       out     = (float*)d_out;

    dim3 gbp((NP + BP_CHUNK - 1) / BP_CHUNK, NB);   // 12 x 64
    dim3 gls((NP + 255) / 256, NB);                 // 96 x 64
    k_bestprior<<<gbp, 256>>>(priors, targets);
    k_loss<<<gls, 256>>>(loc, conf, priors, targets);
    k_select<<<NB, 1024>>>();
    k_final<<<1, 1024>>>(out);
}

// round 13
// speedup vs baseline: 1.8272x; 1.8272x over previous
#include <cuda_runtime.h>
#include <math.h>

#define NB 64
#define NP 24564
#define NM 16
#define NC 21
#define BP_CHUNK 2048   // priors per k_bestprior block (12 chunks cover 24576)

// ---------------- scratch (device globals; zero-initialized at load) ----------------
__device__ float              g_mined[NB * NP];  // loss_c_mined (0 for pos)
__device__ unsigned long long g_bp[NB * NM];     // best prior key per truth
__device__ float              g_loss_l;
__device__ float              g_loss_c;
__device__ float              g_pos_conf[NB];
__device__ int                g_num_pos[NB];

// ---------------- best prior per truth: warp-per-truth, div-free tracking ----------------
__global__ void k_bestprior(const float* __restrict__ priors,
                            const float* __restrict__ targets) {
    int b    = blockIdx.y;
    int tid  = threadIdx.x;
    int wj   = tid >> 5;          // warp = truth index (16 warps)
    int lane = tid & 31;
    __shared__ float s_tr[NM][4];

    if (tid < NM * 4) {
        int m = tid >> 2, c = tid & 3;
        s_tr[m][c] = targets[(b * NM + m) * 5 + c];
    }
    __syncthreads();

    float tx1 = s_tr[wj][0], ty1 = s_tr[wj][1];
    float tx2 = s_tr[wj][2], ty2 = s_tr[wj][3];
    float ta  = (tx2 - tx1) * (ty2 - ty1);

    // running best as (inter, denom, p); compare via cross-mult (denoms > 0)
    float bi = -1.f, bd = 1.f;
    int   bp = 0;

    int p0   = blockIdx.x * BP_CHUNK;
    int pend = p0 + BP_CHUNK; if (pend > NP) pend = NP;
    for (int p = p0 + lane; p < pend; p += 32) {
        float4 pr = ((const float4*)priors)[p];
        float px1 = pr.x - pr.z * 0.5f, py1 = pr.y - pr.w * 0.5f;
        float px2 = pr.x + pr.z * 0.5f, py2 = pr.y + pr.w * 0.5f;
        float pa  = (px2 - px1) * (py2 - py1);
        float iw  = fminf(tx2, px2) - fmaxf(tx1, px1);
        float ih  = fminf(ty2, py2) - fmaxf(ty1, py1);
        iw = fmaxf(iw, 0.f); ih = fmaxf(ih, 0.f);
        float inter = iw * ih;
        float denom = ta + pa - inter;
        if (inter * bd > bi * denom) { bi = inter; bd = denom; bp = p; }
        // ascending p within thread -> strict > keeps first occurrence on ties
    }

    unsigned long long key = 0ull;
    if (bi >= 0.f) {
        float iou = bi / bd;
        key = ((unsigned long long)__float_as_uint(iou) << 32)
            | (unsigned long long)(0xFFFFFFFFu - (unsigned)bp);  // tie -> smaller p
    }
    #pragma unroll
    for (int off = 16; off; off >>= 1) {
        unsigned long long o = __shfl_down_sync(0xFFFFFFFFu, key, off);
        if (o > key) key = o;
    }
    if (lane == 0) atomicMax(&g_bp[b * NM + wj], key);
}

// ---------------- fused match + losses (HBM-bound heavy pass, div-free match) ----------------
__global__ void k_loss(const float* __restrict__ loc,
                       const float* __restrict__ conf,
                       const float* __restrict__ priors,
                       const float* __restrict__ targets) {
    int b   = blockIdx.y;
    int tid = threadIdx.x;
    int p0  = blockIdx.x * 256;
    __shared__ float    s_conf[256 * NC];
    __shared__ float    s_tr[NM][5];
    __shared__ float    s_area[NM];
    __shared__ unsigned s_op[NM];               // forced prior index per truth
    __shared__ float    r_ll[8], r_pc[8];
    __shared__ int      r_np[8];

    int nvalid = NP - p0; if (nvalid > 256) nvalid = 256;
    // (b*NP+p0)*21 floats is 16B-aligned and nvalid*21 divisible by 4 -> pure float4.
    const float4* src4 = (const float4*)(conf + ((size_t)b * NP + p0) * NC);
    float4*       dst4 = (float4*)s_conf;
    int n4 = (nvalid * NC) >> 2;
    for (int i = tid; i < n4; i += 256) dst4[i] = src4[i];
    if (tid < NM * 5) s_tr[tid / 5][tid % 5] = targets[b * NM * 5 + tid];
    if (tid >= 128 && tid < 128 + NM) {
        int j = tid - 128;
        s_op[j] = 0xFFFFFFFFu - (unsigned)(g_bp[b * NM + j] & 0xFFFFFFFFull);
    }
    __syncthreads();
    if (tid < NM)
        s_area[tid] = (s_tr[tid][2] - s_tr[tid][0]) * (s_tr[tid][3] - s_tr[tid][1]);
    __syncthreads();

    int p = p0 + tid;
    float my_ll = 0.f, my_pc = 0.f;
    int   my_np = 0;

    if (p < NP) {
        // inline best-truth match, div-free: track (inter, denom) of the best
        float4 pr = ((const float4*)priors)[p];
        float px1 = pr.x - pr.z * 0.5f, py1 = pr.y - pr.w * 0.5f;
        float px2 = pr.x + pr.z * 0.5f, py2 = pr.y + pr.w * 0.5f;
        float pa  = (px2 - px1) * (py2 - py1);
        float bi = -1.f, bd = 1.f;
        int   bestj = 0;
        #pragma unroll
        for (int j = 0; j < NM; j++) {
            float iw = fminf(s_tr[j][2], px2) - fmaxf(s_tr[j][0], px1);
            float ih = fminf(s_tr[j][3], py2) - fmaxf(s_tr[j][1], py1);
            iw = fmaxf(iw, 0.f); ih = fmaxf(ih, 0.f);
            float inter = iw * ih;
            float denom = s_area[j] + pa - inter;
            if (inter * bd > bi * denom) { bi = inter; bd = denom; bestj = j; }
        }
        bool forced = false;
        #pragma unroll
        for (int j = 0; j < NM; j++)                       // ascending -> last-wins
            if (s_op[j] == (unsigned)p) { bestj = j; forced = true; }
        bool pos = forced || (2.f * bi >= bd);             // iou >= 0.5 (exact: 0.5 is pow2)
        int  ct  = pos ? ((int)s_tr[bestj][4] + 1) : 0;

        // logsumexp without max-subtraction (conf ~ N(0,1); fp32 safe)
        const float* cr = &s_conf[tid * NC];
        float s = 0.f;
        #pragma unroll
        for (int c = 0; c < NC; c++) s += __expf(cr[c]);
        float lca = __logf(s) - cr[ct];

        g_mined[b * NP + p] = pos ? 0.f : lca;

        if (pos) {
            my_pc = lca;
            my_np = 1;
            float4 ld = ((const float4*)loc)[(size_t)b * NP + p];
            float tx1 = s_tr[bestj][0], ty1 = s_tr[bestj][1];
            float tx2 = s_tr[bestj][2], ty2 = s_tr[bestj][3];
            float gx = ((tx1 + tx2) * 0.5f - pr.x) / (0.1f * pr.z);
            float gy = ((ty1 + ty2) * 0.5f - pr.y) / (0.1f * pr.w);
            float gw = logf((tx2 - tx1) / pr.z) / 0.2f;
            float gh = logf((ty2 - ty1) / pr.w) / 0.2f;
            float d, a;
            d = ld.x - gx; a = fabsf(d); my_ll += (a < 1.f) ? (0.5f * d * d) : (a - 0.5f);
            d = ld.y - gy; a = fabsf(d); my_ll += (a < 1.f) ? (0.5f * d * d) : (a - 0.5f);
            d = ld.z - gw; a = fabsf(d); my_ll += (a < 1.f) ? (0.5f * d * d) : (a - 0.5f);
            d = ld.w - gh; a = fabsf(d); my_ll += (a < 1.f) ? (0.5f * d * d) : (a - 0.5f);
        }
    }

    // block reduce
    int lane = tid & 31, wp = tid >> 5;
    for (int off = 16; off; off >>= 1) {
        my_ll += __shfl_down_sync(0xFFFFFFFFu, my_ll, off);
        my_pc += __shfl_down_sync(0xFFFFFFFFu, my_pc, off);
        my_np += __shfl_down_sync(0xFFFFFFFFu, my_np, off);
    }
    if (lane == 0) { r_ll[wp] = my_ll; r_pc[wp] = my_pc; r_np[wp] = my_np; }
    __syncthreads();
    if (tid == 0) {
        float tll = 0.f, tpc = 0.f; int tnp = 0;
        #pragma unroll
        for (int w = 0; w < 8; w++) { tll += r_ll[w]; tpc += r_pc[w]; tnp += r_np[w]; }
        atomicAdd(&g_loss_l, tll);
        atomicAdd(&g_pos_conf[b], tpc);
        atomicAdd(&g_num_pos[b], tnp);
    }
}

// ---------------- hard-negative mining: radix top-k SUM, warp-aggregated histogram ----------------
__global__ void k_select() {
    int b   = blockIdx.x;
    int tid = threadIdx.x;
    int lane = tid & 31;
    __shared__ int      bins[256];
    __shared__ unsigned s_pref;
    __shared__ int      s_krem;
    __shared__ float    r_s[32];

    const float* data = &g_mined[b * NP];

    if (tid == 0) {
        s_pref = 0u;
        long long kk = 3LL * (long long)g_num_pos[b];
        if (kk > NP - 1) kk = NP - 1;
        s_krem = (int)kk;
    }
    if (tid < 256) bins[tid] = 0;
    __syncthreads();

    for (int byte = 3; byte >= 0; --byte) {
        unsigned pref = s_pref;
        int shift = byte * 8;
        for (int i = tid; i < NP; i += 1024) {
            unsigned u = __float_as_uint(data[i]);   // values >= 0 -> bits monotone
            bool ok = (byte == 3) || ((u >> (shift + 8)) == pref);
            if (ok) {
                int bin = (u >> shift) & 255;
                // warp-aggregate: values concentrate in few exponent bins ->
                // one atomic per distinct bin per warp instead of per lane
                unsigned am   = __activemask();
                unsigned mask = __match_any_sync(am, bin);
                int leader    = __ffs(mask) - 1;
                if (lane == leader) atomicAdd(&bins[bin], __popc(mask));
            }
        }
        __syncthreads();
        if (tid == 0) {
            int krem = s_krem, cum = 0, sel = 0;
            for (int t = 255; t >= 0; --t) {
                int c = bins[t];
                if (cum + c >= krem) { sel = t; break; }
                cum += c;
            }
            s_krem = krem - cum;
            s_pref = (s_pref << 8) | (unsigned)sel;
        }
        __syncthreads();
        if (tid < 256) bins[tid] = 0;
        __syncthreads();
    }

    unsigned thr  = s_pref;
    int      krem = s_krem;
    float s = 0.f;
    #pragma unroll 4
    for (int i = tid; i < NP; i += 1024) {
        float v = data[i];
        if (__float_as_uint(v) > thr) s += v;
    }
    int wp = tid >> 5;
    for (int off = 16; off; off >>= 1) s += __shfl_down_sync(0xFFFFFFFFu, s, off);
    if (lane == 0) r_s[wp] = s;
    __syncthreads();
    if (tid == 0) {
        float tot = 0.f;
        #pragma unroll
        for (int w = 0; w < 32; w++) tot += r_s[w];
        tot += (float)krem * __uint_as_float(thr);   // boundary-tied elements
        tot += g_pos_conf[b];                        // pos contribution (pos | neg union)
        atomicAdd(&g_loss_c, tot);
    }
}

// ---------------- finalize + reset accumulators for next graph replay ----------------
__global__ void k_final(float* __restrict__ out) {
    int tid = threadIdx.x;
    if (tid < 32) {
        int n = 0;
        for (int b = tid; b < NB; b += 32) n += g_num_pos[b];
        for (int off = 16; off; off >>= 1) n += __shfl_down_sync(0xFFFFFFFFu, n, off);
        if (tid == 0) {
            float fn = (float)n;
            out[0] = g_loss_l / fn;
            out[1] = g_loss_c / fn;
        }
    }
    __syncthreads();
    // reset so every replay starts from a clean state
    if (tid < NB * NM) g_bp[tid] = 0ull;
    if (tid < NB) { g_pos_conf[tid] = 0.f; g_num_pos[tid] = 0; }
    if (tid == 0) { g_loss_l = 0.f; g_loss_c = 0.f; }
}

// ---------------- launch ----------------
extern "C" void kernel_launch(void* const* d_in, const int* in_sizes, int n_in,
                              void* d_out, int out_size) {
    const float* loc     = (const float*)d_in[0];
    const float* conf    = (const float*)d_in[1];
    const float* priors  = (const float*)d_in[2];
    const float* targets = (const float*)d_in[3];
    float*       out     = (float*)d_out;

    dim3 gbp((NP + BP_CHUNK - 1) / BP_CHUNK, NB);   // 12 x 64, 512 thr (16 warps = 16 truths)
    dim3 gls((NP + 255) / 256, NB);                 // 96 x 64
    k_bestprior<<<gbp, 512>>>(priors, targets);
    k_loss<<<gls, 256>>>(loc, conf, priors, targets);
    k_select<<<NB, 1024>>>();
    k_final<<<1, 1024>>>(out);
}